// round 8
// baseline (speedup 1.0000x reference)
#include <cuda_runtime.h>
#include <cuda_fp16.h>
#include <math.h>
#include <stdint.h>

// ---------------- problem constants ----------------
#define NB    1000      // B
#define NN    20        // neighbors per node
#define D_    172
#define DT_   100
#define E_    272       // D + DT
#define DK_   444       // D + DT + DE
#define KPAD  448       // padded K for the KV GEMM A buffer
#define HD    136       // head dim (E/2)
#define NKV   544       // fused K|V output width
#define QK    192       // padded K for Q gemm (172->192)
#define OK    288       // padded K for Wo gemm (272->288)
#define CST   288       // CTX row stride (fp16, zero-padded)

#define R1    (NB*NN)    // 20000 layer-1 queries
#define ROWS1 (R1*NN)    // 400000 layer-1 kv rows

// ---------------- scratch (device globals; zero-initialized, no allocs) ----------------
__device__ __align__(16) __half g_Ah  [(size_t)ROWS1 * KPAD]; // KV gemm input / MLP input (reused)
__device__ __align__(16) __half g_KVh [(size_t)ROWS1 * NKV];  // fused K|V output
__device__ __align__(16) __half g_Qh  [(size_t)R1 * E_];
__device__ __align__(16) __half g_CTXh[(size_t)R1 * CST];     // pad cols 272-287 stay 0
__device__ __align__(16) __half g_SRCh[(size_t)R1 * QK];      // pad cols 172-191 stay 0
__device__ __align__(16) __half g_Hh  [(size_t)R1 * QK];      // pad cols 172-191 stay 0
__device__ __align__(16) __half g_EMBh[(size_t)R1 * D_];
// fp16 weights (padded)
__device__ __align__(16) __half g_Wqh [(size_t)2 * E_ * QK];
__device__ __align__(16) __half g_WKVh[(size_t)2 * NKV * KPAD];
__device__ __align__(16) __half g_Woh [(size_t)2 * E_ * OK];
__device__ __align__(16) __half g_W1h [(size_t)2 * D_ * KPAD];
__device__ __align__(16) __half g_W2h [(size_t)2 * D_ * QK];
__device__ float g_bKV [2 * NKV];
__device__ float g_CQ  [2 * E_];
__device__ int   g_AM  [R1];

// ============================================================================
// fp16 tensor-core GEMM via mma.sync (HMMA):
//   C[M, N] = A[M, K]fp16 @ W[N, K]fp16^T + bias  (fp32 accum; fp16 or fp32 out)
// 128 threads = 4 warps (2m x 2n), CTA tile 128x128, warp tile 64x64.
// BK=32, 3-stage cp.async ring, ONE __syncthreads per chunk.
// Grid: (ceil(N/128), ceil(M/128)).
// ============================================================================
#define AST 40   // smem row stride (halfs), padded: conflict-free ldmatrix
#define STAGE_H (128 * AST)              // halfs per (A or B) stage
#define HG_SMEM (3 * 2 * STAGE_H * 2)    // 3 stages * (A+B) * sizeof(half) = 61440 B

__device__ __forceinline__ void ldsm_x4(uint32_t* r, uint32_t addr) {
    asm volatile("ldmatrix.sync.aligned.m8n8.x4.shared.b16 {%0,%1,%2,%3}, [%4];"
                 : "=r"(r[0]), "=r"(r[1]), "=r"(r[2]), "=r"(r[3]) : "r"(addr));
}
__device__ __forceinline__ void mma16816(float* d, const uint32_t* a, uint32_t b0, uint32_t b1) {
    asm volatile("mma.sync.aligned.m16n8k16.row.col.f32.f16.f16.f32 "
                 "{%0,%1,%2,%3}, {%4,%5,%6,%7}, {%8,%9}, {%0,%1,%2,%3};"
                 : "+f"(d[0]), "+f"(d[1]), "+f"(d[2]), "+f"(d[3])
                 : "r"(a[0]), "r"(a[1]), "r"(a[2]), "r"(a[3]), "r"(b0), "r"(b1));
}
__device__ __forceinline__ void cp16(uint32_t dst, const void* src, int sz) {
    asm volatile("cp.async.cg.shared.global [%0], [%1], 16, %2;"
                 :: "r"(dst), "l"(src), "r"(sz));
}

template<int HALF_OUT>
__global__ __launch_bounds__(128, 2)
void hgemm(const __half* __restrict__ A, int lda,
           const __half* __restrict__ W,
           const float* __restrict__ bias,
           const int* __restrict__ rowzero,
           void* __restrict__ Cout, int ldc,
           int M, int N, int K, int relu)
{
    extern __shared__ __half smem[];
    __half* sA = smem;                    // 3 stages of 128x32 (stride AST)
    __half* sB = smem + 3 * STAGE_H;      // 3 stages of 128x32

    const int tid  = threadIdx.x;
    const int lane = tid & 31, wid = tid >> 5;
    const int warp_m = wid & 1, warp_n = wid >> 1;
    const int m0 = blockIdx.y * 128;
    const int n0 = blockIdx.x * 128;
    const int nchunks = K >> 5;

    float acc[4][8][4];
    #pragma unroll
    for (int i = 0; i < 4; i++)
        #pragma unroll
        for (int j = 0; j < 8; j++)
            #pragma unroll
            for (int q = 0; q < 4; q++) acc[i][j][q] = 0.f;

    auto loadA = [&](int s, int k0) {
        #pragma unroll
        for (int c = tid; c < 512; c += 128) {
            int row = c >> 2, seg = c & 3;
            int gm = m0 + row;
            uint32_t dst = (uint32_t)__cvta_generic_to_shared(&sA[s * STAGE_H + row * AST + seg * 8]);
            cp16(dst, A + (size_t)gm * lda + k0 + seg * 8, gm < M ? 16 : 0);
        }
    };
    auto loadB = [&](int s, int k0) {
        #pragma unroll
        for (int c = tid; c < 512; c += 128) {
            int row = c >> 2, seg = c & 3;
            int gn = n0 + row;
            uint32_t dst = (uint32_t)__cvta_generic_to_shared(&sB[s * STAGE_H + row * AST + seg * 8]);
            cp16(dst, W + (size_t)gn * K + k0 + seg * 8, gn < N ? 16 : 0);
        }
    };

    auto computeStage = [&](int s) {
        const __half* As = sA + s * STAGE_H;
        const __half* Bs = sB + s * STAGE_H;
        #pragma unroll
        for (int kk = 0; kk < 2; ++kk) {
            uint32_t afr[4][4];
            #pragma unroll
            for (int i = 0; i < 4; ++i) {
                uint32_t addr = (uint32_t)__cvta_generic_to_shared(
                    &As[(warp_m * 64 + i * 16 + (lane & 15)) * AST + kk * 16 + (lane >> 4) * 8]);
                ldsm_x4(afr[i], addr);
            }
            uint32_t bfr[4][4];
            #pragma unroll
            for (int j = 0; j < 4; ++j) {
                int nrow = warp_n * 64 + j * 16 + ((lane >> 4) << 3) + (lane & 7);
                int kcol = kk * 16 + ((lane >> 3) & 1) * 8;
                uint32_t addr = (uint32_t)__cvta_generic_to_shared(&Bs[nrow * AST + kcol]);
                ldsm_x4(bfr[j], addr);
            }
            #pragma unroll
            for (int i = 0; i < 4; ++i)
                #pragma unroll
                for (int j = 0; j < 8; ++j)
                    mma16816(acc[i][j], afr[i], bfr[j >> 1][(j & 1) * 2], bfr[j >> 1][(j & 1) * 2 + 1]);
        }
    };

    // prologue: prefetch 2 stages
    loadA(0, 0); loadB(0, 0);
    asm volatile("cp.async.commit_group;" ::: "memory");
    if (nchunks > 1) {
        loadA(1, 32); loadB(1, 32);
        asm volatile("cp.async.commit_group;" ::: "memory");
    }

    for (int c = 0; c < nchunks; ++c) {
        asm volatile("cp.async.wait_group 1;" ::: "memory");  // stage c data ready
        __syncthreads();                                       // all warps done with stage (c-1)%3 buffer reuse
        if (c + 2 < nchunks) {
            int s = (c + 2) % 3;
            loadA(s, (c + 2) * 32); loadB(s, (c + 2) * 32);
            asm volatile("cp.async.commit_group;" ::: "memory");
        } else {
            asm volatile("cp.async.commit_group;" ::: "memory"); // keep group accounting uniform
        }
        computeStage(c % 3);
    }

    // ---- epilogue ----
    #pragma unroll
    for (int i = 0; i < 4; ++i) {
        int row = m0 + warp_m * 64 + i * 16 + (lane >> 2);
        #pragma unroll
        for (int j = 0; j < 8; ++j) {
            int col = n0 + warp_n * 64 + j * 8 + (lane & 3) * 2;
            if (col < N) {
                float b0 = bias[col], b1 = bias[col + 1];
                #pragma unroll
                for (int half_ = 0; half_ < 2; ++half_) {
                    int r = row + half_ * 8;
                    if (r < M) {
                        int rz = rowzero ? rowzero[r] : 0;
                        float v0 = rz ? 0.f : (acc[i][j][half_ * 2]     + b0);
                        float v1 = rz ? 0.f : (acc[i][j][half_ * 2 + 1] + b1);
                        if (relu) { v0 = fmaxf(v0, 0.f); v1 = fmaxf(v1, 0.f); }
                        if (HALF_OUT) {
                            *(__half2*)((__half*)Cout + (size_t)r * ldc + col) =
                                __floats2half2_rn(v0, v1);
                        } else {
                            float* cp = (float*)Cout + (size_t)r * ldc + col;
                            cp[0] = v0; cp[1] = v1;
                        }
                    }
                }
            }
        }
    }
}

// ---------------- generic weight convert+pad: dst[N][KP] <- src[N][Ksrc](first Kcopy) ----
__global__ void convert_pad(const float* __restrict__ src, __half* __restrict__ dst,
                            int N, int Ksrc, int Kcopy, int KP)
{
    long total = (long)N * KP;
    for (long i = (long)blockIdx.x * blockDim.x + threadIdx.x; i < total;
         i += (long)gridDim.x * blockDim.x) {
        int k = (int)(i % KP);
        int n = (int)(i / KP);
        dst[i] = __float2half(k < Kcopy ? src[(size_t)n * Ksrc + k] : 0.f);
    }
}

// ---------------- bias concat for fused KV ----------------
__global__ void concat_bkv(const float* __restrict__ bk, const float* __restrict__ bv)
{
    int l = blockIdx.x, n = threadIdx.x;
    if (n < NKV)
        g_bKV[l * NKV + n] = (n < E_) ? bk[l * E_ + n] : bv[l * E_ + n - E_];
}

// ---------------- constant part of q: c_q[l] = cos(b_time) @ Wq[l][:,172:].T + bq[l] ----
__global__ void cq_kernel(const float* __restrict__ Wq, const float* __restrict__ bq,
                          const float* __restrict__ b_time)
{
    int l = blockIdx.x;
    int n = threadIdx.x;
    if (n < E_) {
        float s = bq[l*E_ + n];
        const float* w = Wq + (size_t)l*E_*E_ + (size_t)n*E_ + D_;
        #pragma unroll 4
        for (int j = 0; j < DT_; j++) s += cosf(b_time[j]) * w[j];
        g_CQ[l*E_ + n] = s;
    }
}

// ---------------- gather memory rows -> fp16 SRC (stride QK, pads stay 0) ----------------
__global__ void gather_h(const float* __restrict__ src, const int* __restrict__ idx,
                         __half* __restrict__ dst, int rows)
{
    long total = (long)rows * D_;
    for (long i = (long)blockIdx.x*blockDim.x + threadIdx.x; i < total;
         i += (long)gridDim.x * blockDim.x) {
        int r = (int)(i / D_);
        int k = (int)(i % D_);
        dst[(size_t)r * QK + k] = __float2half(src[(size_t)idx[r]*D_ + k]);
    }
}

// ---------------- copy SRC into MLP-input cols [272, 444) of g_Ah ----------------
__global__ void copy_src(int rows)
{
    long total = (long)rows * D_;
    for (long i = (long)blockIdx.x*blockDim.x + threadIdx.x; i < total;
         i += (long)gridDim.x * blockDim.x) {
        int r = (int)(i / D_);
        int k = (int)(i % D_);
        g_Ah[(size_t)r * KPAD + E_ + k] = g_SRCh[(size_t)r * QK + k];
    }
}

// ---------------- build fp16 KV GEMM rows (warp per row):
// [neigh(172) | cos(dt*w+b)(100) | edge(172) | 0pad(4)]
__global__ void build_kv(const float* __restrict__ memf,      // layer1: gather via neighbors
                         const __half* __restrict__ memh,     // layer2: row m direct (stride D_)
                         const int* __restrict__ neighbors,
                         const float* __restrict__ edge_features,
                         const int* __restrict__ edge_idxs,
                         const float* __restrict__ edge_times,
                         const float* __restrict__ timestamps, int ts_div,
                         const float* __restrict__ w_time, const float* __restrict__ b_time,
                         int rows)
{
    int warp = threadIdx.x >> 5, lane = threadIdx.x & 31;
    int m = blockIdx.x * 4 + warp;
    if (m >= rows) return;

    __half2* out = (__half2*)(g_Ah + (size_t)m * KPAD);
    const float*  nbf = memf ? memf + (size_t)neighbors[m] * D_ : nullptr;
    const __half* nbh = memf ? nullptr : memh + (size_t)m * D_;
    float dt = timestamps[m / ts_div] - edge_times[m];
    const float* ef = edge_features + (size_t)edge_idxs[m] * D_;

    #pragma unroll
    for (int i = lane; i < KPAD/2; i += 32) {
        int k = i * 2;
        float a, b;
        if (k < D_) {
            if (nbf) { a = nbf[k]; b = nbf[k+1]; }
            else     { __half2 h = *(const __half2*)(nbh + k); float2 f = __half22float2(h); a = f.x; b = f.y; }
        } else if (k < E_) {
            int j = k - D_;
            a = cosf(dt*w_time[j]   + b_time[j]);
            b = cosf(dt*w_time[j+1] + b_time[j+1]);
        } else if (k < DK_) {
            a = ef[k - E_]; b = ef[k - E_ + 1];
        } else { a = 0.f; b = 0.f; }
        out[i] = __floats2half2_rn(a, b);
    }
}

// ---------------- attention: warp per query row, fp16 in/out ----------------
__global__ void attn_kernel(const __half* __restrict__ Q, const __half* __restrict__ KV,
                            const int* __restrict__ nbrs,
                            __half* __restrict__ CTX, int* __restrict__ AM, int R)
{
    __shared__ float qsh[4][E_];
    int warp = threadIdx.x >> 5, lane = threadIdx.x & 31;
    int row = blockIdx.x*4 + warp;
    if (row >= R) return;

    for (int d = lane; d < E_; d += 32)
        qsh[warp][d] = __half2float(Q[(size_t)row*E_ + d]);
    __syncwarp();

    const float scale = rsqrtf((float)HD);
    float a[2][NN];

    #pragma unroll
    for (int h = 0; h < 2; h++) {
        const float* qh = qsh[warp] + h*HD;
        for (int n = 0; n < NN; n++) {
            const __half2* k2 = (const __half2*)(KV + ((size_t)row*NN + n)*NKV + h*HD);
            float s = 0.f;
            for (int i = lane; i < HD/2; i += 32) {
                float2 kf = __half22float2(k2[i]);
                s += qh[2*i]*kf.x + qh[2*i+1]*kf.y;
            }
            #pragma unroll
            for (int o = 16; o; o >>= 1) s += __shfl_xor_sync(0xffffffffu, s, o);
            a[h][n] = s * scale;
        }
    }

    int allm = 1;
    #pragma unroll
    for (int n = 0; n < NN; n++) {
        int nb = nbrs[(size_t)row*NN + n];
        if (nb == 0) { a[0][n] = -1e9f; a[1][n] = -1e9f; }
        else allm = 0;
    }

    #pragma unroll
    for (int h = 0; h < 2; h++) {
        float mx = -3.4e38f;
        #pragma unroll
        for (int n = 0; n < NN; n++) mx = fmaxf(mx, a[h][n]);
        float ssum = 0.f;
        #pragma unroll
        for (int n = 0; n < NN; n++) { float e = expf(a[h][n] - mx); a[h][n] = e; ssum += e; }
        float inv = 1.f / ssum;
        #pragma unroll
        for (int n = 0; n < NN; n++) a[h][n] *= inv;
    }
    if (lane == 0) AM[row] = allm;

    for (int i = lane; i < E_/2; i += 32) {
        int h = (2*i) >= HD;
        float ax = 0.f, ay = 0.f;
        #pragma unroll
        for (int n = 0; n < NN; n++) {
            const __half2* v2 = (const __half2*)(KV + ((size_t)row*NN + n)*NKV + E_);
            float2 vf = __half22float2(v2[i]);
            ax += a[h][n] * vf.x;
            ay += a[h][n] * vf.y;
        }
        *(__half2*)(CTX + (size_t)row*CST + 2*i) = __floats2half2_rn(ax, ay);
    }
}

// ---------------- host helpers ----------------
static void launch_hgemm_h(const __half* A, int lda, const __half* W, const float* bias,
                           const int* rz, __half* C, int ldc, int M, int N, int K, int relu)
{
    dim3 grid((N + 127)/128, (M + 127)/128);
    hgemm<1><<<grid, 128, HG_SMEM>>>(A, lda, W, bias, rz, (void*)C, ldc, M, N, K, relu);
}
static void launch_hgemm_f(const __half* A, int lda, const __half* W, const float* bias,
                           const int* rz, float* C, int ldc, int M, int N, int K, int relu)
{
    dim3 grid((N + 127)/128, (M + 127)/128);
    hgemm<0><<<grid, 128, HG_SMEM>>>(A, lda, W, bias, rz, (void*)C, ldc, M, N, K, relu);
}

extern "C" void kernel_launch(void* const* d_in, const int* in_sizes, int n_in,
                              void* d_out, int out_size)
{
    const float* memory = (const float*)d_in[0];
    const float* edgef  = (const float*)d_in[1];
    const int*   srcn   = (const int*)  d_in[2];
    const float* ts     = (const float*)d_in[3];
    const int*   nb1    = (const int*)  d_in[4];
    const int*   ei1    = (const int*)  d_in[5];
    const float* et1    = (const float*)d_in[6];
    const int*   nb2    = (const int*)  d_in[7];
    const int*   ei2    = (const int*)  d_in[8];
    const float* et2    = (const float*)d_in[9];
    const float* w_time = (const float*)d_in[10];
    const float* b_time = (const float*)d_in[11];
    const float* Wq = (const float*)d_in[12];
    const float* bq = (const float*)d_in[13];
    const float* Wk = (const float*)d_in[14];
    const float* bk = (const float*)d_in[15];
    const float* Wv = (const float*)d_in[16];
    const float* bv = (const float*)d_in[17];
    const float* Wo = (const float*)d_in[18];
    const float* bo = (const float*)d_in[19];
    const float* W1 = (const float*)d_in[20];
    const float* b1 = (const float*)d_in[21];
    const float* W2 = (const float*)d_in[22];
    const float* b2 = (const float*)d_in[23];
    float* out = (float*)d_out;

    __half *pAh, *pKVh, *pQh, *pCTXh, *pSRCh, *pHh, *pEMBh;
    __half *pWqh, *pWKVh, *pWoh, *pW1h, *pW2h;
    float *pbKV, *pCQ;
    int* pAM;
    cudaGetSymbolAddress((void**)&pAh,   g_Ah);
    cudaGetSymbolAddress((void**)&pKVh,  g_KVh);
    cudaGetSymbolAddress((void**)&pQh,   g_Qh);
    cudaGetSymbolAddress((void**)&pCTXh, g_CTXh);
    cudaGetSymbolAddress((void**)&pSRCh, g_SRCh);
    cudaGetSymbolAddress((void**)&pHh,   g_Hh);
    cudaGetSymbolAddress((void**)&pEMBh, g_EMBh);
    cudaGetSymbolAddress((void**)&pWqh,  g_Wqh);
    cudaGetSymbolAddress((void**)&pWKVh, g_WKVh);
    cudaGetSymbolAddress((void**)&pWoh,  g_Woh);
    cudaGetSymbolAddress((void**)&pW1h,  g_W1h);
    cudaGetSymbolAddress((void**)&pW2h,  g_W2h);
    cudaGetSymbolAddress((void**)&pbKV,  g_bKV);
    cudaGetSymbolAddress((void**)&pCQ,   g_CQ);
    cudaGetSymbolAddress((void**)&pAM,   g_AM);

    cudaFuncSetAttribute(hgemm<1>, cudaFuncAttributeMaxDynamicSharedMemorySize, HG_SMEM);
    cudaFuncSetAttribute(hgemm<0>, cudaFuncAttributeMaxDynamicSharedMemorySize, HG_SMEM);

    // ---- weight conversion (tiny) ----
    for (int l = 0; l < 2; ++l) {
        convert_pad<<<64, 256>>>(Wq + (size_t)l*E_*E_,  pWqh  + (size_t)l*E_*QK,            E_, E_,  D_,  QK);
        convert_pad<<<128,256>>>(Wk + (size_t)l*E_*DK_, pWKVh + (size_t)l*NKV*KPAD,          E_, DK_, DK_, KPAD);
        convert_pad<<<128,256>>>(Wv + (size_t)l*E_*DK_, pWKVh + (size_t)l*NKV*KPAD + (size_t)E_*KPAD, E_, DK_, DK_, KPAD);
        convert_pad<<<64, 256>>>(Wo + (size_t)l*E_*E_,  pWoh  + (size_t)l*E_*OK,            E_, E_,  E_,  OK);
        convert_pad<<<128,256>>>(W1 + (size_t)l*D_*DK_, pW1h  + (size_t)l*D_*KPAD,          D_, DK_, DK_, KPAD);
        convert_pad<<<64, 256>>>(W2 + (size_t)l*D_*D_,  pW2h  + (size_t)l*D_*QK,            D_, D_,  D_,  QK);
    }
    concat_bkv<<<2, NKV>>>(bk, bv);
    cq_kernel<<<2, E_>>>(Wq, bq, b_time);

    const size_t WQs = (size_t)E_*QK, WKVs = (size_t)NKV*KPAD, WOs = (size_t)E_*OK,
                 W1s = (size_t)D_*KPAD, W2s = (size_t)D_*QK;

    // ================= Layer 1 (l=0): 20000 queries x 20 neighbors =================
    gather_h<<<(R1*D_ + 255)/256, 256>>>(memory, nb1, pSRCh, R1);
    launch_hgemm_h(pSRCh, QK, pWqh, pCQ, nullptr, pQh, E_, R1, E_, QK, 0);

    build_kv<<<(ROWS1 + 3)/4, 128>>>(memory, nullptr, nb2, edgef, ei2, et2, ts, NN*NN,
                                     w_time, b_time, ROWS1);
    launch_hgemm_h(pAh, KPAD, pWKVh, pbKV, nullptr, pKVh, NKV, ROWS1, NKV, KPAD, 0);

    attn_kernel<<<(R1 + 3)/4, 128>>>(pQh, pKVh, nb2, pCTXh, pAM, R1);

    launch_hgemm_h(pCTXh, CST, pWoh, bo, pAM, pAh, KPAD, R1, E_, OK, 0);  // O -> g_Ah cols 0-271
    copy_src<<<(R1*D_ + 255)/256, 256>>>(R1);                              // SRC -> cols 272-443
    launch_hgemm_h(pAh, KPAD, pW1h, b1, nullptr, pHh, QK, R1, D_, KPAD, 1);
    launch_hgemm_h(pHh, QK, pW2h, b2, nullptr, pEMBh, D_, R1, D_, QK, 0);

    // ================= Layer 2 (l=1): 1000 queries x 20 neighbors =================
    gather_h<<<(NB*D_ + 255)/256, 256>>>(memory, srcn, pSRCh, NB);
    launch_hgemm_h(pSRCh, QK, pWqh + WQs, pCQ + E_, nullptr, pQh, E_, NB, E_, QK, 0);

    build_kv<<<(R1 + 3)/4, 128>>>(nullptr, pEMBh, nb1, edgef, ei1, et1, ts, NN,
                                  w_time, b_time, R1);
    launch_hgemm_h(pAh, KPAD, pWKVh + WKVs, pbKV + NKV, nullptr, pKVh, NKV, R1, NKV, KPAD, 0);

    attn_kernel<<<(NB + 3)/4, 128>>>(pQh, pKVh, nb1, pCTXh, pAM, NB);

    launch_hgemm_h(pCTXh, CST, pWoh + WOs, bo + E_, pAM, pAh, KPAD, NB, E_, OK, 0);
    copy_src<<<(NB*D_ + 255)/256, 256>>>(NB);
    launch_hgemm_h(pAh, KPAD, pW1h + W1s, b1 + D_, nullptr, pHh, QK, NB, D_, KPAD, 1);
    launch_hgemm_f(pHh, QK, pW2h + W2s, b2 + D_, nullptr, out, D_, NB, D_, QK, 0);
}

// round 9
// speedup vs baseline: 1.0893x; 1.0893x over previous
#include <cuda_runtime.h>
#include <cuda_fp16.h>
#include <math.h>
#include <stdint.h>

// ---------------- problem constants ----------------
#define NB    1000      // B
#define NN    20        // neighbors per node
#define D_    172
#define DT_   100
#define E_    272       // D + DT
#define DK_   444       // D + DT + DE
#define KPAD  448       // padded K for full KV GEMM (layer 2)
#define TEK   288       // padded K for layer-1 te GEMM (100+172 -> 288)
#define HD    136       // head dim (E/2)
#define NKV   544       // fused K|V output width
#define QK    192       // padded K for Q gemm / mem gemm (172->192)
#define OK    288       // padded K for Wo gemm (272->288)
#define CST   288       // CTX row stride (fp16, zero-padded)
#define NNODE 100000

#define R1    (NB*NN)    // 20000 layer-1 queries
#define ROWS1 (R1*NN)    // 400000 layer-1 kv rows

// ---------------- scratch (device globals; zero-initialized, no allocs) ----------------
__device__ __align__(16) __half g_Ah   [(size_t)ROWS1 * TEK];   // te rows (L1) / full rows (L2, 448<=2*288 ok: sized by max)
__device__ __align__(16) __half g_Afull[(size_t)R1 * KPAD];     // layer-2 full KV input + MLP input
__device__ __align__(16) __half g_KVh  [(size_t)ROWS1 * NKV];   // fused K|V output
__device__ __align__(16) __half g_MEMh [(size_t)NNODE * QK];    // fp16 memory, stride 192 (pads stay 0)
__device__ __align__(16) __half g_MEMKV[(size_t)NNODE * NKV];   // mem @ Wkv_mem (no bias)
__device__ __align__(16) __half g_Qh   [(size_t)R1 * E_];
__device__ __align__(16) __half g_CTXh [(size_t)R1 * CST];      // pad cols 272-287 stay 0
__device__ __align__(16) __half g_SRCh [(size_t)R1 * QK];       // pad cols 172-191 stay 0
__device__ __align__(16) __half g_Hh   [(size_t)R1 * QK];       // pad cols 172-191 stay 0
__device__ __align__(16) __half g_EMBh [(size_t)R1 * D_];
// fp16 weights (padded)
__device__ __align__(16) __half g_Wqh   [(size_t)2 * E_ * QK];
__device__ __align__(16) __half g_WKVm  [(size_t)NKV * QK];     // layer1 mem part  [544][192]
__device__ __align__(16) __half g_WKVte [(size_t)NKV * TEK];    // layer1 te part   [544][288]
__device__ __align__(16) __half g_WKVfull[(size_t)NKV * KPAD];  // layer2 full      [544][448]
__device__ __align__(16) __half g_Woh   [(size_t)2 * E_ * OK];
__device__ __align__(16) __half g_W1h   [(size_t)2 * D_ * KPAD];
__device__ __align__(16) __half g_W2h   [(size_t)2 * D_ * QK];
__device__ float g_bKV  [2 * NKV];
__device__ float g_zero [NKV];          // stays 0
__device__ float g_CQ   [2 * E_];
__device__ int   g_AM   [R1];

// ============================================================================
// fp16 tensor-core GEMM via mma.sync (HMMA)  -- round-7 proven config:
//   C[M, N] = A[M, K] @ W[N, K]^T + bias [+ addsrc[addidx[row]]]  (fp32 accum)
// CTA tile 128x96, BK=32, cp.async double buffer, 256 thr (warps 4m x 2n).
// ============================================================================
#define AST 40
#define BST 40

__device__ __forceinline__ void ldsm_x4(uint32_t* r, uint32_t addr) {
    asm volatile("ldmatrix.sync.aligned.m8n8.x4.shared.b16 {%0,%1,%2,%3}, [%4];"
                 : "=r"(r[0]), "=r"(r[1]), "=r"(r[2]), "=r"(r[3]) : "r"(addr));
}
__device__ __forceinline__ void mma16816(float* d, const uint32_t* a, uint32_t b0, uint32_t b1) {
    asm volatile("mma.sync.aligned.m16n8k16.row.col.f32.f16.f16.f32 "
                 "{%0,%1,%2,%3}, {%4,%5,%6,%7}, {%8,%9}, {%0,%1,%2,%3};"
                 : "+f"(d[0]), "+f"(d[1]), "+f"(d[2]), "+f"(d[3])
                 : "r"(a[0]), "r"(a[1]), "r"(a[2]), "r"(a[3]), "r"(b0), "r"(b1));
}
__device__ __forceinline__ void cp16(uint32_t dst, const void* src, int sz) {
    asm volatile("cp.async.cg.shared.global [%0], [%1], 16, %2;"
                 :: "r"(dst), "l"(src), "r"(sz));
}

template<int HALF_OUT>
__global__ __launch_bounds__(256)
void hgemm(const __half* __restrict__ A, int lda,
           const __half* __restrict__ W,
           const float* __restrict__ bias,
           const int* __restrict__ rowzero,
           const __half* __restrict__ addsrc,     // optional epilogue gather-add
           const int* __restrict__ addidx,
           void* __restrict__ Cout, int ldc,
           int M, int N, int K, int relu)
{
    __shared__ __half sA[2][128 * AST];
    __shared__ __half sB[2][96 * BST];

    const int tid  = threadIdx.x;
    const int lane = tid & 31, wid = tid >> 5;
    const int warp_m = wid & 3, warp_n = wid >> 2;
    const int m0 = blockIdx.y * 128;
    const int n0 = blockIdx.x * 96;
    const int nchunks = K >> 5;

    float acc[2][6][4];
    #pragma unroll
    for (int i = 0; i < 2; i++)
        #pragma unroll
        for (int j = 0; j < 6; j++)
            #pragma unroll
            for (int q = 0; q < 4; q++) acc[i][j][q] = 0.f;

    auto loadA = [&](int s, int k0) {
        #pragma unroll
        for (int c = tid; c < 512; c += 256) {
            int row = c >> 2, seg = c & 3;
            int gm = m0 + row;
            uint32_t dst = (uint32_t)__cvta_generic_to_shared(&sA[s][row * AST + seg * 8]);
            cp16(dst, A + (size_t)gm * lda + k0 + seg * 8, gm < M ? 16 : 0);
        }
    };
    auto loadB = [&](int s, int k0) {
        #pragma unroll
        for (int c = tid; c < 384; c += 256) {
            int row = c >> 2, seg = c & 3;
            int gn = n0 + row;
            uint32_t dst = (uint32_t)__cvta_generic_to_shared(&sB[s][row * BST + seg * 8]);
            cp16(dst, W + (size_t)gn * K + k0 + seg * 8, gn < N ? 16 : 0);
        }
    };

    auto computeStage = [&](int s) {
        #pragma unroll
        for (int kk = 0; kk < 2; ++kk) {
            uint32_t afr[2][4];
            #pragma unroll
            for (int i = 0; i < 2; ++i) {
                uint32_t addr = (uint32_t)__cvta_generic_to_shared(
                    &sA[s][(warp_m * 32 + i * 16 + (lane & 15)) * AST + kk * 16 + (lane >> 4) * 8]);
                ldsm_x4(afr[i], addr);
            }
            uint32_t bfr[3][4];
            #pragma unroll
            for (int j = 0; j < 3; ++j) {
                int nrow = warp_n * 48 + j * 16 + ((lane >> 4) << 3) + (lane & 7);
                int kcol = kk * 16 + ((lane >> 3) & 1) * 8;
                uint32_t addr = (uint32_t)__cvta_generic_to_shared(&sB[s][nrow * BST + kcol]);
                ldsm_x4(bfr[j], addr);
            }
            #pragma unroll
            for (int i = 0; i < 2; ++i)
                #pragma unroll
                for (int j = 0; j < 6; ++j)
                    mma16816(acc[i][j], afr[i], bfr[j >> 1][(j & 1) * 2], bfr[j >> 1][(j & 1) * 2 + 1]);
        }
    };

    loadA(0, 0); loadB(0, 0);
    asm volatile("cp.async.commit_group;" ::: "memory");

    for (int c = 0; c < nchunks; ++c) {
        if (c + 1 < nchunks) {
            loadA((c + 1) & 1, (c + 1) * 32);
            loadB((c + 1) & 1, (c + 1) * 32);
            asm volatile("cp.async.commit_group;" ::: "memory");
            asm volatile("cp.async.wait_group 1;" ::: "memory");
        } else {
            asm volatile("cp.async.wait_group 0;" ::: "memory");
        }
        __syncthreads();
        computeStage(c & 1);
        __syncthreads();
    }

    // ---- epilogue ----
    #pragma unroll
    for (int i = 0; i < 2; ++i) {
        #pragma unroll
        for (int half_ = 0; half_ < 2; ++half_) {
            int r = m0 + warp_m * 32 + i * 16 + (lane >> 2) + half_ * 8;
            if (r >= M) continue;
            int rz = rowzero ? rowzero[r] : 0;
            const __half* arow = addsrc ? addsrc + (size_t)addidx[r] * ldc : nullptr;
            #pragma unroll
            for (int j = 0; j < 6; ++j) {
                int col = n0 + warp_n * 48 + j * 8 + (lane & 3) * 2;
                if (col < N) {
                    float v0 = acc[i][j][half_ * 2]     + bias[col];
                    float v1 = acc[i][j][half_ * 2 + 1] + bias[col + 1];
                    if (arow) {
                        float2 af = __half22float2(*(const __half2*)(arow + col));
                        v0 += af.x; v1 += af.y;
                    }
                    if (rz) { v0 = 0.f; v1 = 0.f; }
                    if (relu) { v0 = fmaxf(v0, 0.f); v1 = fmaxf(v1, 0.f); }
                    if (HALF_OUT) {
                        *(__half2*)((__half*)Cout + (size_t)r * ldc + col) =
                            __floats2half2_rn(v0, v1);
                    } else {
                        float* cp = (float*)Cout + (size_t)r * ldc + col;
                        cp[0] = v0; cp[1] = v1;
                    }
                }
            }
        }
    }
}

// ---------------- fused weight conversion: one launch, static job table ----------------
struct CvtJob { int srcSel; long srcOff; int N; int Ksrc; int koff; int Kcopy; int KP; int dstSel; long dstOff; };
__constant__ CvtJob c_jobs[14] = {
    {0, 0,                 E_, E_,  0,   D_,  QK,   0, 0},                 // Wq l0
    {0, (long)E_*E_,       E_, E_,  0,   D_,  QK,   0, (long)E_*QK},       // Wq l1
    {1, 0,                 E_, DK_, 0,   D_,  QK,   1, 0},                 // Wk mem (l0)
    {2, 0,                 E_, DK_, 0,   D_,  QK,   1, (long)E_*QK},       // Wv mem (l0)
    {1, 0,                 E_, DK_, D_,  272, TEK,  2, 0},                 // Wk te  (l0)
    {2, 0,                 E_, DK_, D_,  272, TEK,  2, (long)E_*TEK},      // Wv te  (l0)
    {1, (long)E_*DK_,      E_, DK_, 0,   DK_, KPAD, 3, 0},                 // Wk full (l1)
    {2, (long)E_*DK_,      E_, DK_, 0,   DK_, KPAD, 3, (long)E_*KPAD},     // Wv full (l1)
    {3, 0,                 E_, E_,  0,   E_,  OK,   4, 0},                 // Wo l0
    {3, (long)E_*E_,       E_, E_,  0,   E_,  OK,   4, (long)E_*OK},       // Wo l1
    {4, 0,                 D_, DK_, 0,   DK_, KPAD, 5, 0},                 // W1 l0
    {4, (long)D_*DK_,      D_, DK_, 0,   DK_, KPAD, 5, (long)D_*KPAD},     // W1 l1
    {5, 0,                 D_, D_,  0,   D_,  QK,   6, 0},                 // W2 l0
    {5, (long)D_*D_,       D_, D_,  0,   D_,  QK,   6, (long)D_*QK},       // W2 l1
};

__global__ void convert_all(const float* __restrict__ Wq, const float* __restrict__ Wk,
                            const float* __restrict__ Wv, const float* __restrict__ Wo,
                            const float* __restrict__ W1, const float* __restrict__ W2)
{
    CvtJob j = c_jobs[blockIdx.y];
    const float* srcTab[6] = {Wq, Wk, Wv, Wo, W1, W2};
    __half* dstTab[7] = {g_Wqh, g_WKVm, g_WKVte, g_WKVfull, g_Woh, g_W1h, g_W2h};
    const float* src = srcTab[j.srcSel] + j.srcOff;
    __half* dst = dstTab[j.dstSel] + j.dstOff;
    long total = (long)j.N * j.KP;
    for (long i = (long)blockIdx.x * blockDim.x + threadIdx.x; i < total;
         i += (long)gridDim.x * blockDim.x) {
        int k = (int)(i % j.KP);
        int n = (int)(i / j.KP);
        dst[i] = __float2half(k < j.Kcopy ? src[(size_t)n * j.Ksrc + j.koff + k] : 0.f);
    }
}

// ---------------- memory -> fp16 (stride QK, pads stay 0) ----------------
__global__ void memconv(const float* __restrict__ mem)
{
    long total = (long)NNODE * D_;
    for (long i = (long)blockIdx.x*blockDim.x + threadIdx.x; i < total;
         i += (long)gridDim.x * blockDim.x) {
        int r = (int)(i / D_);
        int k = (int)(i % D_);
        g_MEMh[(size_t)r * QK + k] = __float2half(mem[i]);
    }
}

// ---------------- fp16 row gather from g_MEMh (both stride QK), uint4 copies ------------
__global__ void gather16(const int* __restrict__ idx, __half* __restrict__ dst, int rows)
{
    long total = (long)rows * 24;   // 24 uint4 per 192-half row
    for (long i = (long)blockIdx.x*blockDim.x + threadIdx.x; i < total;
         i += (long)gridDim.x * blockDim.x) {
        int r = (int)(i / 24);
        int s = (int)(i % 24);
        ((uint4*)(dst + (size_t)r * QK))[s] =
            ((const uint4*)(g_MEMh + (size_t)idx[r] * QK))[s];
    }
}

// ---------------- bias concat for fused KV ----------------
__global__ void concat_bkv(const float* __restrict__ bk, const float* __restrict__ bv)
{
    int l = blockIdx.x, n = threadIdx.x;
    if (n < NKV)
        g_bKV[l * NKV + n] = (n < E_) ? bk[l * E_ + n] : bv[l * E_ + n - E_];
}

// ---------------- constant part of q ----------------
__global__ void cq_kernel(const float* __restrict__ Wq, const float* __restrict__ bq,
                          const float* __restrict__ b_time)
{
    int l = blockIdx.x;
    int n = threadIdx.x;
    if (n < E_) {
        float s = bq[l*E_ + n];
        const float* w = Wq + (size_t)l*E_*E_ + (size_t)n*E_ + D_;
        #pragma unroll 4
        for (int j = 0; j < DT_; j++) s += cosf(b_time[j]) * w[j];
        g_CQ[l*E_ + n] = s;
    }
}

// ---------------- copy SRC into MLP-input cols [272, 444) of g_Afull ----------------
__global__ void copy_src(int rows)
{
    long total = (long)rows * D_;
    for (long i = (long)blockIdx.x*blockDim.x + threadIdx.x; i < total;
         i += (long)gridDim.x * blockDim.x) {
        int r = (int)(i / D_);
        int k = (int)(i % D_);
        g_Afull[(size_t)r * KPAD + E_ + k] = g_SRCh[(size_t)r * QK + k];
    }
}

// ---------------- layer-1 te rows (warp per row): [cos(100) | edge(172) | pad16] -------
__global__ void build_te(const float* __restrict__ edge_features,
                         const int* __restrict__ edge_idxs,
                         const float* __restrict__ edge_times,
                         const float* __restrict__ timestamps,
                         const float* __restrict__ w_time, const float* __restrict__ b_time,
                         int rows)
{
    int warp = threadIdx.x >> 5, lane = threadIdx.x & 31;
    int m = blockIdx.x * 4 + warp;
    if (m >= rows) return;

    __half2* out = (__half2*)(g_Ah + (size_t)m * TEK);
    float dt = timestamps[m / (NN*NN)] - edge_times[m];
    const float* ef = edge_features + (size_t)edge_idxs[m] * D_;

    #pragma unroll
    for (int i = lane; i < TEK/2; i += 32) {
        int k = i * 2;
        float a, b;
        if (k < DT_) {
            a = cosf(dt*w_time[k]   + b_time[k]);
            b = cosf(dt*w_time[k+1] + b_time[k+1]);
        } else if (k < DT_ + D_) {
            a = ef[k - DT_]; b = ef[k - DT_ + 1];
        } else { a = 0.f; b = 0.f; }
        out[i] = __floats2half2_rn(a, b);
    }
}

// ---------------- layer-2 full rows (warp per row): [emb(172)|cos(100)|edge(172)|pad4] --
__global__ void build_full(const __half* __restrict__ memh,
                           const float* __restrict__ edge_features,
                           const int* __restrict__ edge_idxs,
                           const float* __restrict__ edge_times,
                           const float* __restrict__ timestamps,
                           const float* __restrict__ w_time, const float* __restrict__ b_time,
                           int rows)
{
    int warp = threadIdx.x >> 5, lane = threadIdx.x & 31;
    int m = blockIdx.x * 4 + warp;
    if (m >= rows) return;

    __half2* out = (__half2*)(g_Afull + (size_t)m * KPAD);
    const __half* nbh = memh + (size_t)m * D_;
    float dt = timestamps[m / NN] - edge_times[m];
    const float* ef = edge_features + (size_t)edge_idxs[m] * D_;

    #pragma unroll
    for (int i = lane; i < KPAD/2; i += 32) {
        int k = i * 2;
        float a, b;
        if (k < D_) {
            __half2 h = *(const __half2*)(nbh + k); float2 f = __half22float2(h); a = f.x; b = f.y;
        } else if (k < E_) {
            int j = k - D_;
            a = cosf(dt*w_time[j]   + b_time[j]);
            b = cosf(dt*w_time[j+1] + b_time[j+1]);
        } else if (k < DK_) {
            a = ef[k - E_]; b = ef[k - E_ + 1];
        } else { a = 0.f; b = 0.f; }
        out[i] = __floats2half2_rn(a, b);
    }
}

// ---------------- attention: warp per query row, fp16 in/out ----------------
__global__ void attn_kernel(const __half* __restrict__ Q, const __half* __restrict__ KV,
                            const int* __restrict__ nbrs,
                            __half* __restrict__ CTX, int* __restrict__ AM, int R)
{
    __shared__ float qsh[4][E_];
    int warp = threadIdx.x >> 5, lane = threadIdx.x & 31;
    int row = blockIdx.x*4 + warp;
    if (row >= R) return;

    for (int d = lane; d < E_; d += 32)
        qsh[warp][d] = __half2float(Q[(size_t)row*E_ + d]);
    __syncwarp();

    const float scale = rsqrtf((float)HD);
    float a[2][NN];

    #pragma unroll
    for (int h = 0; h < 2; h++) {
        const float* qh = qsh[warp] + h*HD;
        for (int n = 0; n < NN; n++) {
            const __half2* k2 = (const __half2*)(KV + ((size_t)row*NN + n)*NKV + h*HD);
            float s = 0.f;
            for (int i = lane; i < HD/2; i += 32) {
                float2 kf = __half22float2(k2[i]);
                s += qh[2*i]*kf.x + qh[2*i+1]*kf.y;
            }
            #pragma unroll
            for (int o = 16; o; o >>= 1) s += __shfl_xor_sync(0xffffffffu, s, o);
            a[h][n] = s * scale;
        }
    }

    int allm = 1;
    #pragma unroll
    for (int n = 0; n < NN; n++) {
        int nb = nbrs[(size_t)row*NN + n];
        if (nb == 0) { a[0][n] = -1e9f; a[1][n] = -1e9f; }
        else allm = 0;
    }

    #pragma unroll
    for (int h = 0; h < 2; h++) {
        float mx = -3.4e38f;
        #pragma unroll
        for (int n = 0; n < NN; n++) mx = fmaxf(mx, a[h][n]);
        float ssum = 0.f;
        #pragma unroll
        for (int n = 0; n < NN; n++) { float e = expf(a[h][n] - mx); a[h][n] = e; ssum += e; }
        float inv = 1.f / ssum;
        #pragma unroll
        for (int n = 0; n < NN; n++) a[h][n] *= inv;
    }
    if (lane == 0) AM[row] = allm;

    for (int i = lane; i < E_/2; i += 32) {
        int h = (2*i) >= HD;
        float ax = 0.f, ay = 0.f;
        #pragma unroll
        for (int n = 0; n < NN; n++) {
            const __half2* v2 = (const __half2*)(KV + ((size_t)row*NN + n)*NKV + E_);
            float2 vf = __half22float2(v2[i]);
            ax += a[h][n] * vf.x;
            ay += a[h][n] * vf.y;
        }
        *(__half2*)(CTX + (size_t)row*CST + 2*i) = __floats2half2_rn(ax, ay);
    }
}

// ---------------- host helpers ----------------
static void launch_hgemm_h(const __half* A, int lda, const __half* W, const float* bias,
                           const int* rz, const __half* addsrc, const int* addidx,
                           __half* C, int ldc, int M, int N, int K, int relu)
{
    dim3 grid((N + 95)/96, (M + 127)/128);
    hgemm<1><<<grid, 256>>>(A, lda, W, bias, rz, addsrc, addidx, (void*)C, ldc, M, N, K, relu);
}
static void launch_hgemm_f(const __half* A, int lda, const __half* W, const float* bias,
                           const int* rz, float* C, int ldc, int M, int N, int K, int relu)
{
    dim3 grid((N + 95)/96, (M + 127)/128);
    hgemm<0><<<grid, 256>>>(A, lda, W, bias, rz, nullptr, nullptr, (void*)C, ldc, M, N, K, relu);
}

extern "C" void kernel_launch(void* const* d_in, const int* in_sizes, int n_in,
                              void* d_out, int out_size)
{
    const float* memory = (const float*)d_in[0];
    const float* edgef  = (const float*)d_in[1];
    const int*   srcn   = (const int*)  d_in[2];
    const float* ts     = (const float*)d_in[3];
    const int*   nb1    = (const int*)  d_in[4];
    const int*   ei1    = (const int*)  d_in[5];
    const float* et1    = (const float*)d_in[6];
    const int*   nb2    = (const int*)  d_in[7];
    const int*   ei2    = (const int*)  d_in[8];
    const float* et2    = (const float*)d_in[9];
    const float* w_time = (const float*)d_in[10];
    const float* b_time = (const float*)d_in[11];
    const float* Wq = (const float*)d_in[12];
    const float* bq = (const float*)d_in[13];
    const float* Wk = (const float*)d_in[14];
    const float* bk = (const float*)d_in[15];
    const float* Wv = (const float*)d_in[16];
    const float* bv = (const float*)d_in[17];
    const float* Wo = (const float*)d_in[18];
    const float* bo = (const float*)d_in[19];
    const float* W1 = (const float*)d_in[20];
    const float* b1 = (const float*)d_in[21];
    const float* W2 = (const float*)d_in[22];
    const float* b2 = (const float*)d_in[23];
    float* out = (float*)d_out;

    __half *pAh, *pAfull, *pKVh, *pMEMKV, *pQh, *pCTXh, *pSRCh, *pHh, *pEMBh;
    __half *pWqh, *pWKVm, *pWKVte, *pWKVfull, *pWoh, *pW1h, *pW2h;
    float *pbKV, *pZero, *pCQ;
    int* pAM;
    cudaGetSymbolAddress((void**)&pAh,     g_Ah);
    cudaGetSymbolAddress((void**)&pAfull,  g_Afull);
    cudaGetSymbolAddress((void**)&pKVh,    g_KVh);
    cudaGetSymbolAddress((void**)&pMEMKV,  g_MEMKV);
    cudaGetSymbolAddress((void**)&pQh,     g_Qh);
    cudaGetSymbolAddress((void**)&pCTXh,   g_CTXh);
    cudaGetSymbolAddress((void**)&pSRCh,   g_SRCh);
    cudaGetSymbolAddress((void**)&pHh,     g_Hh);
    cudaGetSymbolAddress((void**)&pEMBh,   g_EMBh);
    cudaGetSymbolAddress((void**)&pWqh,    g_Wqh);
    cudaGetSymbolAddress((void**)&pWKVm,   g_WKVm);
    cudaGetSymbolAddress((void**)&pWKVte,  g_WKVte);
    cudaGetSymbolAddress((void**)&pWKVfull,g_WKVfull);
    cudaGetSymbolAddress((void**)&pWoh,    g_Woh);
    cudaGetSymbolAddress((void**)&pW1h,    g_W1h);
    cudaGetSymbolAddress((void**)&pW2h,    g_W2h);
    cudaGetSymbolAddress((void**)&pbKV,    g_bKV);
    cudaGetSymbolAddress((void**)&pZero,   g_zero);
    cudaGetSymbolAddress((void**)&pCQ,     g_CQ);
    cudaGetSymbolAddress((void**)&pAM,     g_AM);

    __half* pMEMh; cudaGetSymbolAddress((void**)&pMEMh, g_MEMh);

    const size_t WQs = (size_t)E_*QK, WOs = (size_t)E_*OK,
                 W1s = (size_t)D_*KPAD, W2s = (size_t)D_*QK;

    // ---- launch order tuned so ncu (-s 5 -c 1) profiles the big te hgemm (#6) ----
    convert_all<<<dim3(64, 14), 256>>>(Wq, Wk, Wv, Wo, W1, W2);                 // 1
    memconv<<<512, 256>>>(memory);                                               // 2
    // memKV[100000,544] = mem @ Wkv_mem^T  (no bias)
    launch_hgemm_h(pMEMh, QK, pWKVm, pZero, nullptr, nullptr, nullptr,           // 3
                   pMEMKV, NKV, NNODE, NKV, QK, 0);
    build_te<<<(ROWS1 + 3)/4, 128>>>(edgef, ei2, et2, ts, w_time, b_time, ROWS1);// 4
    concat_bkv<<<2, NKV>>>(bk, bv);                                              // 5
    // KV = te @ Wkv_te^T + bKV + memKV[nb2]   <-- profiled launch
    launch_hgemm_h(pAh, TEK, pWKVte, pbKV, nullptr, pMEMKV, nb2,                 // 6
                   pKVh, NKV, ROWS1, NKV, TEK, 0);

    cq_kernel<<<2, E_>>>(Wq, bq, b_time);                                        // 7
    gather16<<<(R1*24 + 255)/256, 256>>>(nb1, pSRCh, R1);                        // 8
    launch_hgemm_h(pSRCh, QK, pWqh, pCQ, nullptr, nullptr, nullptr,
                   pQh, E_, R1, E_, QK, 0);                                      // 9

    attn_kernel<<<(R1 + 3)/4, 128>>>(pQh, pKVh, nb2, pCTXh, pAM, R1);            // 10

    launch_hgemm_h(pCTXh, CST, pWoh, bo, pAM, nullptr, nullptr,
                   pAfull, KPAD, R1, E_, OK, 0);                                 // 11: O -> cols 0-271
    copy_src<<<(R1*D_ + 255)/256, 256>>>(R1);                                    // 12: SRC -> cols 272-443
    launch_hgemm_h(pAfull, KPAD, pW1h, b1, nullptr, nullptr, nullptr,
                   pHh, QK, R1, D_, KPAD, 1);                                    // 13
    launch_hgemm_h(pHh, QK, pW2h, b2, nullptr, nullptr, nullptr,
                   pEMBh, D_, R1, D_, QK, 0);                                    // 14

    // ================= Layer 2 =================
    gather16<<<(NB*24 + 255)/256, 256>>>(srcn, pSRCh, NB);                       // 15
    launch_hgemm_h(pSRCh, QK, pWqh + WQs, pCQ + E_, nullptr, nullptr, nullptr,
                   pQh, E_, NB, E_, QK, 0);                                      // 16

    build_full<<<(R1 + 3)/4, 128>>>(pEMBh, edgef, ei1, et1, ts, w_time, b_time, R1); // 17
    launch_hgemm_h(pAfull, KPAD, pWKVfull, pbKV + NKV, nullptr, nullptr, nullptr,
                   pKVh, NKV, R1, NKV, KPAD, 0);                                 // 18

    attn_kernel<<<(NB + 3)/4, 128>>>(pQh, pKVh, nb1, pCTXh, pAM, NB);            // 19

    launch_hgemm_h(pCTXh, CST, pWoh + WOs, bo + E_, pAM, nullptr, nullptr,
                   pAfull, KPAD, NB, E_, OK, 0);                                 // 20
    copy_src<<<(NB*D_ + 255)/256, 256>>>(NB);                                    // 21
    launch_hgemm_h(pAfull, KPAD, pW1h + W1s, b1 + D_, nullptr, nullptr, nullptr,
                   pHh, QK, NB, D_, KPAD, 1);                                    // 22
    launch_hgemm_f(pHh, QK, pW2h + W2s, b2 + D_, nullptr, out, D_, NB, D_, QK, 0); // 23
}

// round 10
// speedup vs baseline: 1.1495x; 1.0553x over previous
#include <cuda_runtime.h>
#include <cuda_fp16.h>
#include <math.h>
#include <stdint.h>

// ---------------- problem constants ----------------
#define NB    1000      // B
#define NN    20        // neighbors per node
#define D_    172
#define DT_   100
#define E_    272       // D + DT
#define DK_   444       // D + DT + DE
#define KPAD  448       // padded K for full KV GEMM (layer 2)
#define TEK   288       // padded K for layer-1 te GEMM (100+172 -> 288)
#define HD    136       // head dim (E/2)
#define NKV   544       // fused K|V output width
#define QK    192       // padded K for Q gemm / mem gemm (172->192)
#define OK    288       // padded K for Wo gemm (272->288)
#define CST   288       // CTX row stride (fp16, zero-padded)
#define NNODE 100000

#define R1    (NB*NN)    // 20000 layer-1 queries
#define ROWS1 (R1*NN)    // 400000 layer-1 kv rows

// ---------------- scratch (device globals; zero-initialized, no allocs) ----------------
__device__ __align__(16) __half g_Ah   [(size_t)ROWS1 * TEK];   // te rows (L1)
__device__ __align__(16) __half g_Afull[(size_t)R1 * KPAD];     // layer-2 full KV input + MLP input
__device__ __align__(16) __half g_KVh  [(size_t)ROWS1 * NKV];   // fused K|V output
__device__ __align__(16) __half g_MEMh [(size_t)NNODE * QK];    // fp16 memory, stride 192 (pads stay 0)
__device__ __align__(16) __half g_MEMKV[(size_t)NNODE * NKV];   // mem @ Wkv_mem (no bias)
__device__ __align__(16) __half g_Qh   [(size_t)R1 * E_];
__device__ __align__(16) __half g_CTXh [(size_t)R1 * CST];      // pad cols 272-287 stay 0
__device__ __align__(16) __half g_SRCh [(size_t)R1 * QK];       // pad cols 172-191 stay 0
__device__ __align__(16) __half g_Hh   [(size_t)R1 * QK];       // pad cols 172-191 stay 0
__device__ __align__(16) __half g_EMBh [(size_t)R1 * D_];
// fp16 weights (padded)
__device__ __align__(16) __half g_Wqh   [(size_t)2 * E_ * QK];
__device__ __align__(16) __half g_WKVm  [(size_t)NKV * QK];     // layer1 mem part  [544][192]
__device__ __align__(16) __half g_WKVte [(size_t)NKV * TEK];    // layer1 te part   [544][288]
__device__ __align__(16) __half g_WKVfull[(size_t)NKV * KPAD];  // layer2 full      [544][448]
__device__ __align__(16) __half g_Woh   [(size_t)2 * E_ * OK];
__device__ __align__(16) __half g_W1h   [(size_t)2 * D_ * KPAD];
__device__ __align__(16) __half g_W2h   [(size_t)2 * D_ * QK];
__device__ float g_bKV  [2 * NKV];
__device__ float g_zero [NKV];          // stays 0
__device__ float g_CQ   [2 * E_];
__device__ int   g_AM   [R1];

// ============================================================================
// fp16 tensor-core GEMM via mma.sync (HMMA) -- round-7 tile config, 3-stage ring:
//   C[M, N] = A[M, K] @ W[N, K]^T + bias [+ addsrc[addidx[row]]]  (fp32 accum)
// CTA tile 128x96, BK=32, 256 thr (warps 4m x 2n, warp tile 32x48).
// 3-stage cp.async ring, ONE __syncthreads per chunk.
// ============================================================================
#define AST 40
#define BST 40
#define A_STAGE (128 * AST)                 // halfs
#define B_STAGE (96 * BST)                  // halfs
#define HG_SMEM ((3 * (A_STAGE + B_STAGE)) * 2)   // 53760 bytes

__device__ __forceinline__ void ldsm_x4(uint32_t* r, uint32_t addr) {
    asm volatile("ldmatrix.sync.aligned.m8n8.x4.shared.b16 {%0,%1,%2,%3}, [%4];"
                 : "=r"(r[0]), "=r"(r[1]), "=r"(r[2]), "=r"(r[3]) : "r"(addr));
}
__device__ __forceinline__ void mma16816(float* d, const uint32_t* a, uint32_t b0, uint32_t b1) {
    asm volatile("mma.sync.aligned.m16n8k16.row.col.f32.f16.f16.f32 "
                 "{%0,%1,%2,%3}, {%4,%5,%6,%7}, {%8,%9}, {%0,%1,%2,%3};"
                 : "+f"(d[0]), "+f"(d[1]), "+f"(d[2]), "+f"(d[3])
                 : "r"(a[0]), "r"(a[1]), "r"(a[2]), "r"(a[3]), "r"(b0), "r"(b1));
}
__device__ __forceinline__ void cp16(uint32_t dst, const void* src, int sz) {
    asm volatile("cp.async.cg.shared.global [%0], [%1], 16, %2;"
                 :: "r"(dst), "l"(src), "r"(sz));
}

template<int HALF_OUT>
__global__ __launch_bounds__(256)
void hgemm(const __half* __restrict__ A, int lda,
           const __half* __restrict__ W,
           const float* __restrict__ bias,
           const int* __restrict__ rowzero,
           const __half* __restrict__ addsrc,     // optional epilogue gather-add
           const int* __restrict__ addidx,
           void* __restrict__ Cout, int ldc,
           int M, int N, int K, int relu)
{
    extern __shared__ __half smem[];
    __half* sA = smem;                       // 3 stages of 128x32
    __half* sB = smem + 3 * A_STAGE;         // 3 stages of 96x32

    const int tid  = threadIdx.x;
    const int lane = tid & 31, wid = tid >> 5;
    const int warp_m = wid & 3, warp_n = wid >> 2;
    const int m0 = blockIdx.y * 128;
    const int n0 = blockIdx.x * 96;
    const int nchunks = K >> 5;

    float acc[2][6][4];
    #pragma unroll
    for (int i = 0; i < 2; i++)
        #pragma unroll
        for (int j = 0; j < 6; j++)
            #pragma unroll
            for (int q = 0; q < 4; q++) acc[i][j][q] = 0.f;

    auto loadA = [&](int s, int k0) {
        #pragma unroll
        for (int c = tid; c < 512; c += 256) {
            int row = c >> 2, seg = c & 3;
            int gm = m0 + row;
            uint32_t dst = (uint32_t)__cvta_generic_to_shared(&sA[s * A_STAGE + row * AST + seg * 8]);
            cp16(dst, A + (size_t)gm * lda + k0 + seg * 8, gm < M ? 16 : 0);
        }
    };
    auto loadB = [&](int s, int k0) {
        #pragma unroll
        for (int c = tid; c < 384; c += 256) {
            int row = c >> 2, seg = c & 3;
            int gn = n0 + row;
            uint32_t dst = (uint32_t)__cvta_generic_to_shared(&sB[s * B_STAGE + row * BST + seg * 8]);
            cp16(dst, W + (size_t)gn * K + k0 + seg * 8, gn < N ? 16 : 0);
        }
    };

    auto computeStage = [&](int s) {
        const __half* As = sA + s * A_STAGE;
        const __half* Bs = sB + s * B_STAGE;
        #pragma unroll
        for (int kk = 0; kk < 2; ++kk) {
            uint32_t afr[2][4];
            #pragma unroll
            for (int i = 0; i < 2; ++i) {
                uint32_t addr = (uint32_t)__cvta_generic_to_shared(
                    &As[(warp_m * 32 + i * 16 + (lane & 15)) * AST + kk * 16 + (lane >> 4) * 8]);
                ldsm_x4(afr[i], addr);
            }
            uint32_t bfr[3][4];
            #pragma unroll
            for (int j = 0; j < 3; ++j) {
                int nrow = warp_n * 48 + j * 16 + ((lane >> 4) << 3) + (lane & 7);
                int kcol = kk * 16 + ((lane >> 3) & 1) * 8;
                uint32_t addr = (uint32_t)__cvta_generic_to_shared(&Bs[nrow * BST + kcol]);
                ldsm_x4(bfr[j], addr);
            }
            #pragma unroll
            for (int i = 0; i < 2; ++i)
                #pragma unroll
                for (int j = 0; j < 6; ++j)
                    mma16816(acc[i][j], afr[i], bfr[j >> 1][(j & 1) * 2], bfr[j >> 1][(j & 1) * 2 + 1]);
        }
    };

    // prologue: prefetch 2 stages
    loadA(0, 0); loadB(0, 0);
    asm volatile("cp.async.commit_group;" ::: "memory");
    if (nchunks > 1) { loadA(1, 32); loadB(1, 32); }
    asm volatile("cp.async.commit_group;" ::: "memory");

    for (int c = 0; c < nchunks; ++c) {
        asm volatile("cp.async.wait_group 1;" ::: "memory");  // stage c ready
        __syncthreads();                                       // buffer (c+2)%3 drained (was compute c-1)
        if (c + 2 < nchunks) {
            int s = (c + 2) % 3;
            loadA(s, (c + 2) * 32); loadB(s, (c + 2) * 32);
        }
        asm volatile("cp.async.commit_group;" ::: "memory");   // uniform group accounting
        computeStage(c % 3);
    }

    // ---- epilogue ----
    #pragma unroll
    for (int i = 0; i < 2; ++i) {
        #pragma unroll
        for (int half_ = 0; half_ < 2; ++half_) {
            int r = m0 + warp_m * 32 + i * 16 + (lane >> 2) + half_ * 8;
            if (r >= M) continue;
            int rz = rowzero ? rowzero[r] : 0;
            const __half* arow = addsrc ? addsrc + (size_t)addidx[r] * ldc : nullptr;
            #pragma unroll
            for (int j = 0; j < 6; ++j) {
                int col = n0 + warp_n * 48 + j * 8 + (lane & 3) * 2;
                if (col < N) {
                    float v0 = acc[i][j][half_ * 2]     + bias[col];
                    float v1 = acc[i][j][half_ * 2 + 1] + bias[col + 1];
                    if (arow) {
                        float2 af = __half22float2(*(const __half2*)(arow + col));
                        v0 += af.x; v1 += af.y;
                    }
                    if (rz) { v0 = 0.f; v1 = 0.f; }
                    if (relu) { v0 = fmaxf(v0, 0.f); v1 = fmaxf(v1, 0.f); }
                    if (HALF_OUT) {
                        *(__half2*)((__half*)Cout + (size_t)r * ldc + col) =
                            __floats2half2_rn(v0, v1);
                    } else {
                        float* cp = (float*)Cout + (size_t)r * ldc + col;
                        cp[0] = v0; cp[1] = v1;
                    }
                }
            }
        }
    }
}

// ---------------- fused weight conversion: one launch, static job table ----------------
struct CvtJob { int srcSel; long srcOff; int N; int Ksrc; int koff; int Kcopy; int KP; int dstSel; long dstOff; };
__constant__ CvtJob c_jobs[14] = {
    {0, 0,                 E_, E_,  0,   D_,  QK,   0, 0},                 // Wq l0
    {0, (long)E_*E_,       E_, E_,  0,   D_,  QK,   0, (long)E_*QK},       // Wq l1
    {1, 0,                 E_, DK_, 0,   D_,  QK,   1, 0},                 // Wk mem (l0)
    {2, 0,                 E_, DK_, 0,   D_,  QK,   1, (long)E_*QK},       // Wv mem (l0)
    {1, 0,                 E_, DK_, D_,  272, TEK,  2, 0},                 // Wk te  (l0)
    {2, 0,                 E_, DK_, D_,  272, TEK,  2, (long)E_*TEK},      // Wv te  (l0)
    {1, (long)E_*DK_,      E_, DK_, 0,   DK_, KPAD, 3, 0},                 // Wk full (l1)
    {2, (long)E_*DK_,      E_, DK_, 0,   DK_, KPAD, 3, (long)E_*KPAD},     // Wv full (l1)
    {3, 0,                 E_, E_,  0,   E_,  OK,   4, 0},                 // Wo l0
    {3, (long)E_*E_,       E_, E_,  0,   E_,  OK,   4, (long)E_*OK},       // Wo l1
    {4, 0,                 D_, DK_, 0,   DK_, KPAD, 5, 0},                 // W1 l0
    {4, (long)D_*DK_,      D_, DK_, 0,   DK_, KPAD, 5, (long)D_*KPAD},     // W1 l1
    {5, 0,                 D_, D_,  0,   D_,  QK,   6, 0},                 // W2 l0
    {5, (long)D_*D_,       D_, D_,  0,   D_,  QK,   6, (long)D_*QK},       // W2 l1
};

__global__ void convert_all(const float* __restrict__ Wq, const float* __restrict__ Wk,
                            const float* __restrict__ Wv, const float* __restrict__ Wo,
                            const float* __restrict__ W1, const float* __restrict__ W2)
{
    CvtJob j = c_jobs[blockIdx.y];
    const float* srcTab[6] = {Wq, Wk, Wv, Wo, W1, W2};
    __half* dstTab[7] = {g_Wqh, g_WKVm, g_WKVte, g_WKVfull, g_Woh, g_W1h, g_W2h};
    const float* src = srcTab[j.srcSel] + j.srcOff;
    __half* dst = dstTab[j.dstSel] + j.dstOff;
    long total = (long)j.N * j.KP;
    for (long i = (long)blockIdx.x * blockDim.x + threadIdx.x; i < total;
         i += (long)gridDim.x * blockDim.x) {
        int k = (int)(i % j.KP);
        int n = (int)(i / j.KP);
        dst[i] = __float2half(k < j.Kcopy ? src[(size_t)n * j.Ksrc + j.koff + k] : 0.f);
    }
}

// ---------------- memory -> fp16 (stride QK, pads stay 0) ----------------
__global__ void memconv(const float* __restrict__ mem)
{
    long total = (long)NNODE * D_;
    for (long i = (long)blockIdx.x*blockDim.x + threadIdx.x; i < total;
         i += (long)gridDim.x * blockDim.x) {
        int r = (int)(i / D_);
        int k = (int)(i % D_);
        g_MEMh[(size_t)r * QK + k] = __float2half(mem[i]);
    }
}

// ---------------- fp16 row gather from g_MEMh (both stride QK), uint4 copies ------------
__global__ void gather16(const int* __restrict__ idx, __half* __restrict__ dst, int rows)
{
    long total = (long)rows * 24;   // 24 uint4 per 192-half row
    for (long i = (long)blockIdx.x*blockDim.x + threadIdx.x; i < total;
         i += (long)gridDim.x * blockDim.x) {
        int r = (int)(i / 24);
        int s = (int)(i % 24);
        ((uint4*)(dst + (size_t)r * QK))[s] =
            ((const uint4*)(g_MEMh + (size_t)idx[r] * QK))[s];
    }
}

// ---------------- bias concat for fused KV ----------------
__global__ void concat_bkv(const float* __restrict__ bk, const float* __restrict__ bv)
{
    int l = blockIdx.x, n = threadIdx.x;
    if (n < NKV)
        g_bKV[l * NKV + n] = (n < E_) ? bk[l * E_ + n] : bv[l * E_ + n - E_];
}

// ---------------- constant part of q ----------------
__global__ void cq_kernel(const float* __restrict__ Wq, const float* __restrict__ bq,
                          const float* __restrict__ b_time)
{
    int l = blockIdx.x;
    int n = threadIdx.x;
    if (n < E_) {
        float s = bq[l*E_ + n];
        const float* w = Wq + (size_t)l*E_*E_ + (size_t)n*E_ + D_;
        #pragma unroll 4
        for (int j = 0; j < DT_; j++) s += cosf(b_time[j]) * w[j];
        g_CQ[l*E_ + n] = s;
    }
}

// ---------------- copy SRC into MLP-input cols [272, 444) of g_Afull ----------------
__global__ void copy_src(int rows)
{
    long total = (long)rows * D_;
    for (long i = (long)blockIdx.x*blockDim.x + threadIdx.x; i < total;
         i += (long)gridDim.x * blockDim.x) {
        int r = (int)(i / D_);
        int k = (int)(i % D_);
        g_Afull[(size_t)r * KPAD + E_ + k] = g_SRCh[(size_t)r * QK + k];
    }
}

// ---------------- layer-1 te rows (warp per row): [cos(100) | edge(172) | pad16] -------
__global__ void build_te(const float* __restrict__ edge_features,
                         const int* __restrict__ edge_idxs,
                         const float* __restrict__ edge_times,
                         const float* __restrict__ timestamps,
                         const float* __restrict__ w_time, const float* __restrict__ b_time,
                         int rows)
{
    int warp = threadIdx.x >> 5, lane = threadIdx.x & 31;
    int m = blockIdx.x * 4 + warp;
    if (m >= rows) return;

    __half2* out = (__half2*)(g_Ah + (size_t)m * TEK);
    float dt = timestamps[m / (NN*NN)] - edge_times[m];
    const float* ef = edge_features + (size_t)edge_idxs[m] * D_;

    #pragma unroll
    for (int i = lane; i < TEK/2; i += 32) {
        int k = i * 2;
        float a, b;
        if (k < DT_) {
            a = cosf(dt*w_time[k]   + b_time[k]);
            b = cosf(dt*w_time[k+1] + b_time[k+1]);
        } else if (k < DT_ + D_) {
            a = ef[k - DT_]; b = ef[k - DT_ + 1];
        } else { a = 0.f; b = 0.f; }
        out[i] = __floats2half2_rn(a, b);
    }
}

// ---------------- layer-2 full rows (warp per row): [emb(172)|cos(100)|edge(172)|pad4] --
__global__ void build_full(const __half* __restrict__ memh,
                           const float* __restrict__ edge_features,
                           const int* __restrict__ edge_idxs,
                           const float* __restrict__ edge_times,
                           const float* __restrict__ timestamps,
                           const float* __restrict__ w_time, const float* __restrict__ b_time,
                           int rows)
{
    int warp = threadIdx.x >> 5, lane = threadIdx.x & 31;
    int m = blockIdx.x * 4 + warp;
    if (m >= rows) return;

    __half2* out = (__half2*)(g_Afull + (size_t)m * KPAD);
    const __half* nbh = memh + (size_t)m * D_;
    float dt = timestamps[m / NN] - edge_times[m];
    const float* ef = edge_features + (size_t)edge_idxs[m] * D_;

    #pragma unroll
    for (int i = lane; i < KPAD/2; i += 32) {
        int k = i * 2;
        float a, b;
        if (k < D_) {
            __half2 h = *(const __half2*)(nbh + k); float2 f = __half22float2(h); a = f.x; b = f.y;
        } else if (k < E_) {
            int j = k - D_;
            a = cosf(dt*w_time[j]   + b_time[j]);
            b = cosf(dt*w_time[j+1] + b_time[j+1]);
        } else if (k < DK_) {
            a = ef[k - E_]; b = ef[k - E_ + 1];
        } else { a = 0.f; b = 0.f; }
        out[i] = __floats2half2_rn(a, b);
    }
}

// ---------------- attention: warp per query row, fp16 in/out ----------------
__global__ void attn_kernel(const __half* __restrict__ Q, const __half* __restrict__ KV,
                            const int* __restrict__ nbrs,
                            __half* __restrict__ CTX, int* __restrict__ AM, int R)
{
    __shared__ float qsh[4][E_];
    int warp = threadIdx.x >> 5, lane = threadIdx.x & 31;
    int row = blockIdx.x*4 + warp;
    if (row >= R) return;

    for (int d = lane; d < E_; d += 32)
        qsh[warp][d] = __half2float(Q[(size_t)row*E_ + d]);
    __syncwarp();

    const float scale = rsqrtf((float)HD);
    float a[2][NN];

    #pragma unroll
    for (int h = 0; h < 2; h++) {
        const float* qh = qsh[warp] + h*HD;
        for (int n = 0; n < NN; n++) {
            const __half2* k2 = (const __half2*)(KV + ((size_t)row*NN + n)*NKV + h*HD);
            float s = 0.f;
            for (int i = lane; i < HD/2; i += 32) {
                float2 kf = __half22float2(k2[i]);
                s += qh[2*i]*kf.x + qh[2*i+1]*kf.y;
            }
            #pragma unroll
            for (int o = 16; o; o >>= 1) s += __shfl_xor_sync(0xffffffffu, s, o);
            a[h][n] = s * scale;
        }
    }

    int allm = 1;
    #pragma unroll
    for (int n = 0; n < NN; n++) {
        int nb = nbrs[(size_t)row*NN + n];
        if (nb == 0) { a[0][n] = -1e9f; a[1][n] = -1e9f; }
        else allm = 0;
    }

    #pragma unroll
    for (int h = 0; h < 2; h++) {
        float mx = -3.4e38f;
        #pragma unroll
        for (int n = 0; n < NN; n++) mx = fmaxf(mx, a[h][n]);
        float ssum = 0.f;
        #pragma unroll
        for (int n = 0; n < NN; n++) { float e = expf(a[h][n] - mx); a[h][n] = e; ssum += e; }
        float inv = 1.f / ssum;
        #pragma unroll
        for (int n = 0; n < NN; n++) a[h][n] *= inv;
    }
    if (lane == 0) AM[row] = allm;

    for (int i = lane; i < E_/2; i += 32) {
        int h = (2*i) >= HD;
        float ax = 0.f, ay = 0.f;
        #pragma unroll
        for (int n = 0; n < NN; n++) {
            const __half2* v2 = (const __half2*)(KV + ((size_t)row*NN + n)*NKV + E_);
            float2 vf = __half22float2(v2[i]);
            ax += a[h][n] * vf.x;
            ay += a[h][n] * vf.y;
        }
        *(__half2*)(CTX + (size_t)row*CST + 2*i) = __floats2half2_rn(ax, ay);
    }
}

// ---------------- host helpers ----------------
static void launch_hgemm_h(const __half* A, int lda, const __half* W, const float* bias,
                           const int* rz, const __half* addsrc, const int* addidx,
                           __half* C, int ldc, int M, int N, int K, int relu)
{
    dim3 grid((N + 95)/96, (M + 127)/128);
    hgemm<1><<<grid, 256, HG_SMEM>>>(A, lda, W, bias, rz, addsrc, addidx, (void*)C, ldc, M, N, K, relu);
}
static void launch_hgemm_f(const __half* A, int lda, const __half* W, const float* bias,
                           const int* rz, float* C, int ldc, int M, int N, int K, int relu)
{
    dim3 grid((N + 95)/96, (M + 127)/128);
    hgemm<0><<<grid, 256, HG_SMEM>>>(A, lda, W, bias, rz, nullptr, nullptr, (void*)C, ldc, M, N, K, relu);
}

extern "C" void kernel_launch(void* const* d_in, const int* in_sizes, int n_in,
                              void* d_out, int out_size)
{
    const float* memory = (const float*)d_in[0];
    const float* edgef  = (const float*)d_in[1];
    const int*   srcn   = (const int*)  d_in[2];
    const float* ts     = (const float*)d_in[3];
    const int*   nb1    = (const int*)  d_in[4];
    const int*   ei1    = (const int*)  d_in[5];
    const float* et1    = (const float*)d_in[6];
    const int*   nb2    = (const int*)  d_in[7];
    const int*   ei2    = (const int*)  d_in[8];
    const float* et2    = (const float*)d_in[9];
    const float* w_time = (const float*)d_in[10];
    const float* b_time = (const float*)d_in[11];
    const float* Wq = (const float*)d_in[12];
    const float* bq = (const float*)d_in[13];
    const float* Wk = (const float*)d_in[14];
    const float* bk = (const float*)d_in[15];
    const float* Wv = (const float*)d_in[16];
    const float* bv = (const float*)d_in[17];
    const float* Wo = (const float*)d_in[18];
    const float* bo = (const float*)d_in[19];
    const float* W1 = (const float*)d_in[20];
    const float* b1 = (const float*)d_in[21];
    const float* W2 = (const float*)d_in[22];
    const float* b2 = (const float*)d_in[23];
    float* out = (float*)d_out;

    __half *pAh, *pAfull, *pKVh, *pMEMKV, *pQh, *pCTXh, *pSRCh, *pHh, *pEMBh, *pMEMh;
    __half *pWqh, *pWKVm, *pWKVte, *pWKVfull, *pWoh, *pW1h, *pW2h;
    float *pbKV, *pZero, *pCQ;
    int* pAM;
    cudaGetSymbolAddress((void**)&pAh,     g_Ah);
    cudaGetSymbolAddress((void**)&pAfull,  g_Afull);
    cudaGetSymbolAddress((void**)&pKVh,    g_KVh);
    cudaGetSymbolAddress((void**)&pMEMKV,  g_MEMKV);
    cudaGetSymbolAddress((void**)&pQh,     g_Qh);
    cudaGetSymbolAddress((void**)&pCTXh,   g_CTXh);
    cudaGetSymbolAddress((void**)&pSRCh,   g_SRCh);
    cudaGetSymbolAddress((void**)&pHh,     g_Hh);
    cudaGetSymbolAddress((void**)&pEMBh,   g_EMBh);
    cudaGetSymbolAddress((void**)&pMEMh,   g_MEMh);
    cudaGetSymbolAddress((void**)&pWqh,    g_Wqh);
    cudaGetSymbolAddress((void**)&pWKVm,   g_WKVm);
    cudaGetSymbolAddress((void**)&pWKVte,  g_WKVte);
    cudaGetSymbolAddress((void**)&pWKVfull,g_WKVfull);
    cudaGetSymbolAddress((void**)&pWoh,    g_Woh);
    cudaGetSymbolAddress((void**)&pW1h,    g_W1h);
    cudaGetSymbolAddress((void**)&pW2h,    g_W2h);
    cudaGetSymbolAddress((void**)&pbKV,    g_bKV);
    cudaGetSymbolAddress((void**)&pZero,   g_zero);
    cudaGetSymbolAddress((void**)&pCQ,     g_CQ);
    cudaGetSymbolAddress((void**)&pAM,     g_AM);

    cudaFuncSetAttribute(hgemm<1>, cudaFuncAttributeMaxDynamicSharedMemorySize, HG_SMEM);
    cudaFuncSetAttribute(hgemm<0>, cudaFuncAttributeMaxDynamicSharedMemorySize, HG_SMEM);

    const size_t WQs = (size_t)E_*QK, WOs = (size_t)E_*OK,
                 W1s = (size_t)D_*KPAD, W2s = (size_t)D_*QK;

    // ---- launch order: #4 (memKV hgemm) and #6 (te hgemm) are both hgemm for profiling ----
    convert_all<<<dim3(64, 14), 256>>>(Wq, Wk, Wv, Wo, W1, W2);                  // 1
    memconv<<<512, 256>>>(memory);                                               // 2
    build_te<<<(ROWS1 + 3)/4, 128>>>(edgef, ei2, et2, ts, w_time, b_time, ROWS1);// 3
    // memKV[100000,544] = mem @ Wkv_mem^T  (no bias)
    launch_hgemm_h(pMEMh, QK, pWKVm, pZero, nullptr, nullptr, nullptr,           // 4
                   pMEMKV, NKV, NNODE, NKV, QK, 0);
    concat_bkv<<<2, NKV>>>(bk, bv);                                              // 5
    // KV = te @ Wkv_te^T + bKV + memKV[nb2]
    launch_hgemm_h(pAh, TEK, pWKVte, pbKV, nullptr, pMEMKV, nb2,                 // 6
                   pKVh, NKV, ROWS1, NKV, TEK, 0);

    cq_kernel<<<2, E_>>>(Wq, bq, b_time);                                        // 7
    gather16<<<(R1*24 + 255)/256, 256>>>(nb1, pSRCh, R1);                        // 8
    launch_hgemm_h(pSRCh, QK, pWqh, pCQ, nullptr, nullptr, nullptr,
                   pQh, E_, R1, E_, QK, 0);                                      // 9

    attn_kernel<<<(R1 + 3)/4, 128>>>(pQh, pKVh, nb2, pCTXh, pAM, R1);            // 10

    launch_hgemm_h(pCTXh, CST, pWoh, bo, pAM, nullptr, nullptr,
                   pAfull, KPAD, R1, E_, OK, 0);                                 // 11
    copy_src<<<(R1*D_ + 255)/256, 256>>>(R1);                                    // 12
    launch_hgemm_h(pAfull, KPAD, pW1h, b1, nullptr, nullptr, nullptr,
                   pHh, QK, R1, D_, KPAD, 1);                                    // 13
    launch_hgemm_h(pHh, QK, pW2h, b2, nullptr, nullptr, nullptr,
                   pEMBh, D_, R1, D_, QK, 0);                                    // 14

    // ================= Layer 2 =================
    gather16<<<(NB*24 + 255)/256, 256>>>(srcn, pSRCh, NB);                       // 15
    launch_hgemm_h(pSRCh, QK, pWqh + WQs, pCQ + E_, nullptr, nullptr, nullptr,
                   pQh, E_, NB, E_, QK, 0);                                      // 16

    build_full<<<(R1 + 3)/4, 128>>>(pEMBh, edgef, ei1, et1, ts, w_time, b_time, R1); // 17
    launch_hgemm_h(pAfull, KPAD, pWKVfull, pbKV + NKV, nullptr, nullptr, nullptr,
                   pKVh, NKV, R1, NKV, KPAD, 0);                                 // 18

    attn_kernel<<<(NB + 3)/4, 128>>>(pQh, pKVh, nb1, pCTXh, pAM, NB);            // 19

    launch_hgemm_h(pCTXh, CST, pWoh + WOs, bo + E_, pAM, nullptr, nullptr,
                   pAfull, KPAD, NB, E_, OK, 0);                                 // 20
    copy_src<<<(NB*D_ + 255)/256, 256>>>(NB);                                    // 21
    launch_hgemm_h(pAfull, KPAD, pW1h + W1s, b1 + D_, nullptr, nullptr, nullptr,
                   pHh, QK, NB, D_, KPAD, 1);                                    // 22
    launch_hgemm_f(pHh, QK, pW2h + W2s, b2 + D_, nullptr, out, D_, NB, D_, QK, 0); // 23
}